// round 2
// baseline (speedup 1.0000x reference)
#include <cuda_runtime.h>
#include <math.h>

#define B_    8
#define L_    768
#define H_    16
#define DK_   64
#define D_    1024
#define BH_   (B_ * H_)            // 128
#define M_    (B_ * L_)            // 6144
#define SCALE 0.125f

// Scratch (device globals; allocation is forbidden)
__device__ float g_Qp[BH_ * L_ * DK_];                 // [bh][l][dk]
__device__ float g_Kp[BH_ * L_ * DK_];
__device__ float g_Vp[BH_ * L_ * DK_];
__device__ float g_S [(size_t)BH_ * L_ * L_];          // scores -> probs (302MB)
__device__ float g_Rw[(size_t)BH_ * 6 * 128 * 896];    // rel windows (352MB)
__device__ float g_O2[(size_t)M_ * D_];                // attn out, merged layout

// ---------------------------------------------------------------------------
// Generic 128x128x8 SGEMM, 256 threads, 8x8 micro-tile, double-buffered smem.
// MODE 0: projection  (A=X[6144,1024], B=W[1024,1024], +bias,
//                      OUT head-split [bh][l][dk])
// MODE 1: concat scores per bh (A=Qp rows, B = Kp rows (xt<6) or E window rows,
//                      OUT = g_S content or g_Rw window)
// MODE 2: out-projection (A=g_O2[6144,1024], B=Wo, +bias, OUT plain [m][n])
// ---------------------------------------------------------------------------
template<int MODE, int KDIM>
__global__ __launch_bounds__(256, 2)
void sgemm128(const float* __restrict__ Aglob, const float* __restrict__ Bglob,
              const float* __restrict__ bias, float* __restrict__ OUT,
              const float* __restrict__ E)
{
    __shared__ __align__(16) float As[2][8][132];
    __shared__ __align__(16) float Bs[2][8][132];

    const int tid   = threadIdx.x;
    const int ldRow = tid >> 1;        // 0..127
    const int ldK   = (tid & 1) * 4;   // 0 or 4
    const int tx    = tid & 15;
    const int ty    = tid >> 4;

    const float* Aptr;
    const float* Bptr;
    bool bvalid = true;
    int bh = 0, qt = 0, xt = 0;

    if constexpr (MODE == 0 || MODE == 2) {
        Aptr = Aglob + (size_t)(blockIdx.y * 128 + ldRow) * 1024;
        Bptr = Bglob + (size_t)(blockIdx.x * 128 + ldRow) * 1024;
    } else {
        bh = blockIdx.z; qt = blockIdx.y; xt = blockIdx.x;
        Aptr = Aglob + ((size_t)bh * 768 + qt * 128 + ldRow) * 64;
        if (xt < 6) {
            Bptr = Bglob + ((size_t)bh * 768 + xt * 128 + ldRow) * 64;
        } else {
            int j = (640 - 128 * qt) + (xt - 6) * 128 + ldRow;
            bvalid = (j <= 1534);
            Bptr = E + (size_t)(bvalid ? j : 0) * 64;
        }
    }

    // prologue: tile 0 -> buffer 0
    float4 ra = *(const float4*)(Aptr + ldK);
    float4 rb = bvalid ? *(const float4*)(Bptr + ldK)
                       : make_float4(0.f, 0.f, 0.f, 0.f);
    As[0][ldK + 0][ldRow] = ra.x; As[0][ldK + 1][ldRow] = ra.y;
    As[0][ldK + 2][ldRow] = ra.z; As[0][ldK + 3][ldRow] = ra.w;
    Bs[0][ldK + 0][ldRow] = rb.x; Bs[0][ldK + 1][ldRow] = rb.y;
    Bs[0][ldK + 2][ldRow] = rb.z; Bs[0][ldK + 3][ldRow] = rb.w;
    __syncthreads();

    float acc[8][8] = {};
    const int nTiles = KDIM / 8;

    for (int t = 0; t < nTiles; ++t) {
        const int buf = t & 1;
        if (t + 1 < nTiles) {
            ra = *(const float4*)(Aptr + (t + 1) * 8 + ldK);
            rb = bvalid ? *(const float4*)(Bptr + (t + 1) * 8 + ldK)
                        : make_float4(0.f, 0.f, 0.f, 0.f);
        }
#pragma unroll
        for (int kk = 0; kk < 8; ++kk) {
            float a[8], b[8];
            *(float4*)&a[0] = *(const float4*)&As[buf][kk][ty * 4];
            *(float4*)&a[4] = *(const float4*)&As[buf][kk][64 + ty * 4];
            *(float4*)&b[0] = *(const float4*)&Bs[buf][kk][tx * 4];
            *(float4*)&b[4] = *(const float4*)&Bs[buf][kk][64 + tx * 4];
#pragma unroll
            for (int i = 0; i < 8; ++i)
#pragma unroll
                for (int j = 0; j < 8; ++j)
                    acc[i][j] = fmaf(a[i], b[j], acc[i][j]);
        }
        if (t + 1 < nTiles) {
            const int nb = buf ^ 1;
            As[nb][ldK + 0][ldRow] = ra.x; As[nb][ldK + 1][ldRow] = ra.y;
            As[nb][ldK + 2][ldRow] = ra.z; As[nb][ldK + 3][ldRow] = ra.w;
            Bs[nb][ldK + 0][ldRow] = rb.x; Bs[nb][ldK + 1][ldRow] = rb.y;
            Bs[nb][ldK + 2][ldRow] = rb.z; Bs[nb][ldK + 3][ldRow] = rb.w;
        }
        __syncthreads();
    }

    // epilogue
#pragma unroll
    for (int i = 0; i < 8; ++i) {
        const int row = (i < 4) ? (ty * 4 + i) : (64 + ty * 4 + i - 4);
#pragma unroll
        for (int j = 0; j < 8; ++j) {
            const int col = (j < 4) ? (tx * 4 + j) : (64 + tx * 4 + j - 4);
            const float v = acc[i][j];
            if constexpr (MODE == 0) {
                const int m = blockIdx.y * 128 + row;
                const int n = blockIdx.x * 128 + col;
                const int bb = m / 768, l = m - bb * 768;
                const int h = n >> 6, d = n & 63;
                OUT[(((size_t)(bb * 16 + h) * 768) + l) * 64 + d] = v + bias[n];
            } else if constexpr (MODE == 2) {
                const int m = blockIdx.y * 128 + row;
                const int n = blockIdx.x * 128 + col;
                OUT[(size_t)m * 1024 + n] = v + bias[n];
            } else {
                const int q = qt * 128 + row;
                if (xt < 6) {
                    g_S[((size_t)bh * 768 + q) * 768 + xt * 128 + col] = v;
                } else {
                    g_Rw[(((size_t)bh * 6 + qt) * 128 + row) * 896
                         + (xt - 6) * 128 + col] = v;
                }
            }
        }
    }
}

// ---------------------------------------------------------------------------
// av: O2 = P @ V, per bh. Tile 256x64x8, 256 threads, 8x8 micro.
// Writes merged layout O2[(b*768+l)*1024 + h*64 + d].
// ---------------------------------------------------------------------------
__global__ __launch_bounds__(256, 2)
void av_kernel()
{
    __shared__ __align__(16) float As[2][8][264];
    __shared__ __align__(16) float Bs[2][8][68];

    const int tid = threadIdx.x;
    const int bh  = blockIdx.z;
    const int m0  = blockIdx.y * 256;
    const int tx  = tid & 7;     // n
    const int ty  = tid >> 3;    // 0..31 (m)

    const float* P = g_S  + (size_t)bh * 768 * 768 + (size_t)(m0 + tid) * 768;
    const float* V = g_Vp + (size_t)bh * 768 * 64;

    // prologue
    float4 ra0 = *(const float4*)(P + 0);
    float4 ra1 = *(const float4*)(P + 4);
    float4 rb  = make_float4(0.f, 0.f, 0.f, 0.f);
    const int bR = tid >> 4, bC = (tid & 15) * 4;   // tid<128 loads B
    if (tid < 128) rb = *(const float4*)(V + (size_t)bR * 64 + bC);

    As[0][0][tid] = ra0.x; As[0][1][tid] = ra0.y;
    As[0][2][tid] = ra0.z; As[0][3][tid] = ra0.w;
    As[0][4][tid] = ra1.x; As[0][5][tid] = ra1.y;
    As[0][6][tid] = ra1.z; As[0][7][tid] = ra1.w;
    if (tid < 128) { Bs[0][bR][bC+0]=rb.x; Bs[0][bR][bC+1]=rb.y;
                     Bs[0][bR][bC+2]=rb.z; Bs[0][bR][bC+3]=rb.w; }
    __syncthreads();

    float acc[8][8] = {};
    const int nTiles = 768 / 8;

    for (int t = 0; t < nTiles; ++t) {
        const int buf = t & 1;
        if (t + 1 < nTiles) {
            const int k1 = (t + 1) * 8;
            ra0 = *(const float4*)(P + k1);
            ra1 = *(const float4*)(P + k1 + 4);
            if (tid < 128)
                rb = *(const float4*)(V + (size_t)(k1 + bR) * 64 + bC);
        }
#pragma unroll
        for (int kk = 0; kk < 8; ++kk) {
            float a[8], b[8];
            *(float4*)&a[0] = *(const float4*)&As[buf][kk][ty * 4];
            *(float4*)&a[4] = *(const float4*)&As[buf][kk][128 + ty * 4];
            *(float4*)&b[0] = *(const float4*)&Bs[buf][kk][tx * 4];
            *(float4*)&b[4] = *(const float4*)&Bs[buf][kk][32 + tx * 4];
#pragma unroll
            for (int i = 0; i < 8; ++i)
#pragma unroll
                for (int j = 0; j < 8; ++j)
                    acc[i][j] = fmaf(a[i], b[j], acc[i][j]);
        }
        if (t + 1 < nTiles) {
            const int nb = buf ^ 1;
            As[nb][0][tid] = ra0.x; As[nb][1][tid] = ra0.y;
            As[nb][2][tid] = ra0.z; As[nb][3][tid] = ra0.w;
            As[nb][4][tid] = ra1.x; As[nb][5][tid] = ra1.y;
            As[nb][6][tid] = ra1.z; As[nb][7][tid] = ra1.w;
            if (tid < 128) { Bs[nb][bR][bC+0]=rb.x; Bs[nb][bR][bC+1]=rb.y;
                             Bs[nb][bR][bC+2]=rb.z; Bs[nb][bR][bC+3]=rb.w; }
        }
        __syncthreads();
    }

    const int b = bh >> 4, h = bh & 15;
#pragma unroll
    for (int i = 0; i < 8; ++i) {
        const int q = m0 + ((i < 4) ? (ty * 4 + i) : (128 + ty * 4 + i - 4));
#pragma unroll
        for (int j = 0; j < 8; ++j) {
            const int d = (j < 4) ? (tx * 4 + j) : (32 + tx * 4 + j - 4);
            g_O2[((size_t)(b * 768 + q)) * 1024 + h * 64 + d] = acc[i][j];
        }
    }
}

// ---------------------------------------------------------------------------
// Fused rel-add + scale + softmax. One block per (bh,q) row.
// val[k] = SCALE*(S[k] + Rw_row[k - (q&127) + 127]) ; softmax over k.
// ---------------------------------------------------------------------------
__global__ __launch_bounds__(256)
void softmax_rel()
{
    const int row = blockIdx.x;            // bh*768 + q
    const int bh  = row / 768;
    const int q   = row - bh * 768;
    const int qt  = q >> 7, qi = q & 127;

    float* s = g_S + (size_t)row * 768;
    const float* r = g_Rw + (((size_t)bh * 6 + qt) * 128 + qi) * 896 + (127 - qi);

    const int t = threadIdx.x;
    float v0 = SCALE * (s[t]       + r[t]);
    float v1 = SCALE * (s[t + 256] + r[t + 256]);
    float v2 = SCALE * (s[t + 512] + r[t + 512]);

    __shared__ float sred[8];
    __shared__ float sbcast;

    float m = fmaxf(v0, fmaxf(v1, v2));
#pragma unroll
    for (int o = 16; o; o >>= 1) m = fmaxf(m, __shfl_xor_sync(0xffffffffu, m, o));
    if ((t & 31) == 0) sred[t >> 5] = m;
    __syncthreads();
    if (t == 0) {
        float mm = sred[0];
#pragma unroll
        for (int w = 1; w < 8; w++) mm = fmaxf(mm, sred[w]);
        sbcast = mm;
    }
    __syncthreads();
    m = sbcast;

    float e0 = __expf(v0 - m), e1 = __expf(v1 - m), e2 = __expf(v2 - m);
    float ssum = e0 + e1 + e2;
#pragma unroll
    for (int o = 16; o; o >>= 1) ssum += __shfl_xor_sync(0xffffffffu, ssum, o);
    if ((t & 31) == 0) sred[t >> 5] = ssum;
    __syncthreads();
    if (t == 0) {
        float tt = sred[0];
#pragma unroll
        for (int w = 1; w < 8; w++) tt += sred[w];
        sbcast = 1.0f / tt;
    }
    __syncthreads();
    const float inv = sbcast;
    s[t] = e0 * inv; s[t + 256] = e1 * inv; s[t + 512] = e2 * inv;
}

// ---------------------------------------------------------------------------
extern "C" void kernel_launch(void* const* d_in, const int* in_sizes, int n_in,
                              void* d_out, int out_size)
{
    const float* query = (const float*)d_in[0];
    const float* key   = (const float*)d_in[1];
    const float* value = (const float*)d_in[2];
    const float* w_q   = (const float*)d_in[3];
    const float* b_q   = (const float*)d_in[4];
    const float* w_k   = (const float*)d_in[5];
    const float* b_k   = (const float*)d_in[6];
    const float* w_v   = (const float*)d_in[7];
    const float* b_v   = (const float*)d_in[8];
    const float* w_o   = (const float*)d_in[9];
    const float* b_o   = (const float*)d_in[10];
    const float* relE  = (const float*)d_in[11];
    float* out = (float*)d_out;

    float *qp, *kp, *vp, *o2;
    cudaGetSymbolAddress((void**)&qp, g_Qp);
    cudaGetSymbolAddress((void**)&kp, g_Kp);
    cudaGetSymbolAddress((void**)&vp, g_Vp);
    cudaGetSymbolAddress((void**)&o2, g_O2);

    const dim3 gproj(8, 48);
    sgemm128<0, 1024><<<gproj, 256>>>(query, w_q, b_q, qp, nullptr);
    sgemm128<0, 1024><<<gproj, 256>>>(key,   w_k, b_k, kp, nullptr);
    sgemm128<0, 1024><<<gproj, 256>>>(value, w_v, b_v, vp, nullptr);

    sgemm128<1, 64><<<dim3(13, 6, 128), 256>>>(qp, kp, nullptr, nullptr, relE);

    softmax_rel<<<BH_ * L_, 256>>>();

    av_kernel<<<dim3(1, 3, 128), 256>>>();

    sgemm128<2, 1024><<<gproj, 256>>>(o2, w_o, b_o, out, nullptr);
}

// round 4
// speedup vs baseline: 2.4308x; 2.4308x over previous
#include <cuda_runtime.h>
#include <cstdint>

#define B_    8
#define L_    768
#define H_    16
#define DK_   64
#define D_    1024
#define BH_   128
#define M_    6144
#define SCALE 0.125f

// Scratch (device globals; allocation forbidden)
__device__ float g_Qp[BH_ * L_ * DK_];                 // [bh][l][dk]
__device__ float g_Kp[BH_ * L_ * DK_];
__device__ float g_Vt[BH_ * DK_ * L_];                 // V transposed: [bh][dk][l]
__device__ float g_S [(size_t)BH_ * L_ * L_];          // scores -> probs
__device__ float g_Rw[(size_t)BH_ * 6 * 128 * 896];    // rel windows
__device__ float g_O2[(size_t)M_ * D_];                // attn out, merged

__device__ __forceinline__ float to_tf32(float x) {
    float r;
    asm("cvt.rna.tf32.f32 %0, %1;" : "=f"(r) : "f"(x));
    return r;
}

__device__ __forceinline__ void mma_tf32(float* d, const uint32_t* a, const uint32_t* b) {
    asm volatile(
        "mma.sync.aligned.m16n8k8.row.col.f32.tf32.tf32.f32 "
        "{%0,%1,%2,%3}, {%4,%5,%6,%7}, {%8,%9}, {%0,%1,%2,%3};"
        : "+f"(d[0]), "+f"(d[1]), "+f"(d[2]), "+f"(d[3])
        : "r"(a[0]), "r"(a[1]), "r"(a[2]), "r"(a[3]), "r"(b[0]), "r"(b[1]));
}

// ---------------------------------------------------------------------------
// Warp-MMA tf32 GEMM: C[128, TN] = A[128, K] @ B[TN, K]^T  (both K-major)
// MODE 0: Q/K projection   (A=X, B=W, +bias, OUT head-split [bh][l][dk])
// MODE 1: V projection     (writes g_Vt transposed, +bias)
// MODE 2: scores concat    (A=Qp tile, B=Kp tile or E window -> g_S / g_Rw)
// MODE 3: av               (A=g_S probs, B=g_Vt, TN=64, OUT=g_O2 merged)
// MODE 4: out projection   (A=g_O2, B=Wo, +bias, OUT plain)
// Block: 256 threads = 8 warps (2 x 4); warp tile 64 x (TN/4).
// ---------------------------------------------------------------------------
template<int MODE>
__global__ __launch_bounds__(256)
void mma_gemm(const float* __restrict__ Ag, const float* __restrict__ Bg,
              const float* __restrict__ bias, float* __restrict__ OUT,
              const float* __restrict__ E)
{
    constexpr int TN   = (MODE == 3) ? 64 : 128;
    constexpr int KDIM = (MODE == 2) ? 64 : (MODE == 3 ? 768 : 1024);
    constexpr int NT   = KDIM / 8;          // K tiles of 8
    constexpr int WN   = TN / 4;            // warp n extent (32 or 16)
    constexpr int NTN  = WN / 8;            // n mma tiles per warp (4 or 2)

    __shared__ float As[2][8][136];
    __shared__ float Bs[2][8][136];

    const int tid  = threadIdx.x;
    const int wid  = tid >> 5;
    const int lane = tid & 31;
    const int wm   = (wid & 1) * 64;        // warp m offset
    const int wn   = (wid >> 1) * WN;       // warp n offset
    const int g4   = lane >> 2;             // 0..7
    const int cq   = lane & 3;              // 0..3

    // global operand pointers
    const float* Arow; const float* Brow;
    int lda, ldb;
    int bh = 0, qt = 0, xt = 0, mt_ = 0;
    bool relmode = false; int jbase = 0;
    if constexpr (MODE == 0 || MODE == 1 || MODE == 4) {
        Arow = Ag + (size_t)(blockIdx.y * 128) * 1024; lda = 1024;
        Brow = Bg + (size_t)(blockIdx.x * 128) * 1024; ldb = 1024;
    } else if constexpr (MODE == 2) {
        bh = blockIdx.z; qt = blockIdx.y; xt = blockIdx.x;
        Arow = g_Qp + ((size_t)bh * 768 + qt * 128) * 64; lda = 64;
        if (xt < 6) { Brow = g_Kp + ((size_t)bh * 768 + xt * 128) * 64; ldb = 64; }
        else { relmode = true; jbase = (640 - 128 * qt) + (xt - 6) * 128;
               Brow = E + (size_t)jbase * 64; ldb = 64; }
    } else {  // MODE 3
        bh = blockIdx.z; mt_ = blockIdx.y;
        Arow = g_S  + (size_t)bh * 768 * 768 + (size_t)(mt_ * 128) * 768; lda = 768;
        Brow = g_Vt + (size_t)bh * 64 * 768;                              ldb = 768;
    }

    // loader indices: A 256 float4 (r=tid>>1, seg=(tid&1)*4); B TN rows
    const int lr = tid >> 1, lseg = (tid & 1) * 4;
    const bool bload = (TN == 128) || (tid < 128);

    auto load_tile = [&](int t, int buf) {
        const int k0 = t * 8;
        float4 va = *(const float4*)(Arow + (size_t)lr * lda + k0 + lseg);
        As[buf][lseg + 0][lr] = to_tf32(va.x);
        As[buf][lseg + 1][lr] = to_tf32(va.y);
        As[buf][lseg + 2][lr] = to_tf32(va.z);
        As[buf][lseg + 3][lr] = to_tf32(va.w);
        if (bload) {
            float4 vb;
            if (MODE == 2 && relmode && (jbase + lr > 1534))
                vb = make_float4(0.f, 0.f, 0.f, 0.f);
            else
                vb = *(const float4*)(Brow + (size_t)lr * ldb + k0 + lseg);
            Bs[buf][lseg + 0][lr] = to_tf32(vb.x);
            Bs[buf][lseg + 1][lr] = to_tf32(vb.y);
            Bs[buf][lseg + 2][lr] = to_tf32(vb.z);
            Bs[buf][lseg + 3][lr] = to_tf32(vb.w);
        }
    };

    float acc[4][NTN][4];
#pragma unroll
    for (int i = 0; i < 4; ++i)
#pragma unroll
        for (int j = 0; j < NTN; ++j)
#pragma unroll
            for (int k = 0; k < 4; ++k) acc[i][j][k] = 0.f;

    load_tile(0, 0);
    __syncthreads();

    for (int t = 0; t < NT; ++t) {
        const int buf = t & 1;
        float4 pa, pb;
        const bool nx = (t + 1 < NT);
        if (nx) {
            const int k1 = (t + 1) * 8;
            pa = *(const float4*)(Arow + (size_t)lr * lda + k1 + lseg);
            if (bload) {
                if (MODE == 2 && relmode && (jbase + lr > 1534))
                    pb = make_float4(0.f, 0.f, 0.f, 0.f);
                else
                    pb = *(const float4*)(Brow + (size_t)lr * ldb + k1 + lseg);
            }
        }

        // fragments
        uint32_t afr[4][4], bfr[NTN][2];
#pragma unroll
        for (int m = 0; m < 4; ++m) {
            const int m0 = wm + m * 16;
            afr[m][0] = __float_as_uint(As[buf][cq    ][m0 + g4    ]);
            afr[m][1] = __float_as_uint(As[buf][cq    ][m0 + g4 + 8]);
            afr[m][2] = __float_as_uint(As[buf][cq + 4][m0 + g4    ]);
            afr[m][3] = __float_as_uint(As[buf][cq + 4][m0 + g4 + 8]);
        }
#pragma unroll
        for (int n = 0; n < NTN; ++n) {
            const int n0 = wn + n * 8;
            bfr[n][0] = __float_as_uint(Bs[buf][cq    ][n0 + g4]);
            bfr[n][1] = __float_as_uint(Bs[buf][cq + 4][n0 + g4]);
        }
#pragma unroll
        for (int m = 0; m < 4; ++m)
#pragma unroll
            for (int n = 0; n < NTN; ++n)
                mma_tf32(acc[m][n], afr[m], bfr[n]);

        if (nx) {
            const int nb = buf ^ 1;
            As[nb][lseg + 0][lr] = to_tf32(pa.x);
            As[nb][lseg + 1][lr] = to_tf32(pa.y);
            As[nb][lseg + 2][lr] = to_tf32(pa.z);
            As[nb][lseg + 3][lr] = to_tf32(pa.w);
            if (bload) {
                Bs[nb][lseg + 0][lr] = to_tf32(pb.x);
                Bs[nb][lseg + 1][lr] = to_tf32(pb.y);
                Bs[nb][lseg + 2][lr] = to_tf32(pb.z);
                Bs[nb][lseg + 3][lr] = to_tf32(pb.w);
            }
        }
        __syncthreads();
    }

    // ---- epilogue: C fragment rows g4 / g4+8, cols cq*2, cq*2+1 ----
#pragma unroll
    for (int m = 0; m < 4; ++m) {
#pragma unroll
        for (int n = 0; n < NTN; ++n) {
            const int col = wn + n * 8 + cq * 2;
#pragma unroll
            for (int h2 = 0; h2 < 2; ++h2) {
                const int row = wm + m * 16 + g4 + h2 * 8;
                const float c0 = acc[m][n][h2 * 2 + 0];
                const float c1 = acc[m][n][h2 * 2 + 1];
                if constexpr (MODE == 0) {
                    const int mg = blockIdx.y * 128 + row;
                    const int bb = mg / 768, l = mg - bb * 768;
                    const int ng = blockIdx.x * 128 + col;
                    const int hh = ng >> 6, dd = ng & 63;
                    float* dst = OUT + (((size_t)(bb * 16 + hh) * 768) + l) * 64 + dd;
                    dst[0] = c0 + bias[ng];
                    dst[1] = c1 + bias[ng + 1];
                } else if constexpr (MODE == 1) {
                    const int mg = blockIdx.y * 128 + row;
                    const int bb = mg / 768, l = mg - bb * 768;
                    const int ng = blockIdx.x * 128 + col;
                    const int hh = ng >> 6, dd = ng & 63;
                    g_Vt[((size_t)(bb * 16 + hh) * 64 + dd    ) * 768 + l] = c0 + bias[ng];
                    g_Vt[((size_t)(bb * 16 + hh) * 64 + dd + 1) * 768 + l] = c1 + bias[ng + 1];
                } else if constexpr (MODE == 2) {
                    const int q = qt * 128 + row;
                    float* dst = (xt < 6)
                        ? g_S  + ((size_t)bh * 768 + q) * 768 + xt * 128 + col
                        : g_Rw + (((size_t)bh * 6 + qt) * 128 + row) * 896
                               + (xt - 6) * 128 + col;
                    dst[0] = c0; dst[1] = c1;
                } else if constexpr (MODE == 3) {
                    const int q = mt_ * 128 + row;
                    const int b = bh >> 4, hh = bh & 15;
                    float* dst = g_O2 + ((size_t)(b * 768 + q)) * 1024 + hh * 64 + col;
                    dst[0] = c0; dst[1] = c1;
                } else {  // MODE 4
                    const int mg = blockIdx.y * 128 + row;
                    const int ng = blockIdx.x * 128 + col;
                    float* dst = OUT + (size_t)mg * 1024 + ng;
                    dst[0] = c0 + bias[ng];
                    dst[1] = c1 + bias[ng + 1];
                }
            }
        }
    }
}

// ---------------------------------------------------------------------------
// Fused rel-add + scale + softmax (proven). One block per (bh,q) row.
// ---------------------------------------------------------------------------
__global__ __launch_bounds__(256)
void softmax_rel()
{
    const int row = blockIdx.x;
    const int bh  = row / 768;
    const int q   = row - bh * 768;
    const int qt  = q >> 7, qi = q & 127;

    float* s = g_S + (size_t)row * 768;
    const float* r = g_Rw + (((size_t)bh * 6 + qt) * 128 + qi) * 896 + (127 - qi);

    const int t = threadIdx.x;
    float v0 = SCALE * (s[t]       + r[t]);
    float v1 = SCALE * (s[t + 256] + r[t + 256]);
    float v2 = SCALE * (s[t + 512] + r[t + 512]);

    __shared__ float sred[8];
    __shared__ float sbcast;

    float m = fmaxf(v0, fmaxf(v1, v2));
#pragma unroll
    for (int o = 16; o; o >>= 1) m = fmaxf(m, __shfl_xor_sync(0xffffffffu, m, o));
    if ((t & 31) == 0) sred[t >> 5] = m;
    __syncthreads();
    if (t == 0) {
        float mm = sred[0];
#pragma unroll
        for (int w = 1; w < 8; w++) mm = fmaxf(mm, sred[w]);
        sbcast = mm;
    }
    __syncthreads();
    m = sbcast;

    float e0 = __expf(v0 - m), e1 = __expf(v1 - m), e2 = __expf(v2 - m);
    float ssum = e0 + e1 + e2;
#pragma unroll
    for (int o = 16; o; o >>= 1) ssum += __shfl_xor_sync(0xffffffffu, ssum, o);
    if ((t & 31) == 0) sred[t >> 5] = ssum;
    __syncthreads();
    if (t == 0) {
        float tt = sred[0];
#pragma unroll
        for (int w = 1; w < 8; w++) tt += sred[w];
        sbcast = 1.0f / tt;
    }
    __syncthreads();
    const float inv = sbcast;
    s[t] = e0 * inv; s[t + 256] = e1 * inv; s[t + 512] = e2 * inv;
}

// ---------------------------------------------------------------------------
extern "C" void kernel_launch(void* const* d_in, const int* in_sizes, int n_in,
                              void* d_out, int out_size)
{
    const float* query = (const float*)d_in[0];
    const float* key   = (const float*)d_in[1];
    const float* value = (const float*)d_in[2];
    const float* w_q   = (const float*)d_in[3];
    const float* b_q   = (const float*)d_in[4];
    const float* w_k   = (const float*)d_in[5];
    const float* b_k   = (const float*)d_in[6];
    const float* w_v   = (const float*)d_in[7];
    const float* b_v   = (const float*)d_in[8];
    const float* w_o   = (const float*)d_in[9];
    const float* b_o   = (const float*)d_in[10];
    const float* relE  = (const float*)d_in[11];
    float* out = (float*)d_out;

    float *qp, *kp, *o2;
    cudaGetSymbolAddress((void**)&qp, g_Qp);
    cudaGetSymbolAddress((void**)&kp, g_Kp);
    cudaGetSymbolAddress((void**)&o2, g_O2);

    mma_gemm<0><<<dim3(8, 48), 256>>>(query, w_q, b_q, qp, nullptr);
    mma_gemm<0><<<dim3(8, 48), 256>>>(key,   w_k, b_k, kp, nullptr);
    mma_gemm<1><<<dim3(8, 48), 256>>>(value, w_v, b_v, nullptr, nullptr);

    mma_gemm<2><<<dim3(13, 6, 128), 256>>>(nullptr, nullptr, nullptr, nullptr, relE);

    softmax_rel<<<BH_ * L_, 256>>>();

    mma_gemm<3><<<dim3(1, 6, 128), 256>>>(nullptr, nullptr, nullptr, nullptr, nullptr);

    mma_gemm<4><<<dim3(8, 48), 256>>>(o2, w_o, b_o, out, nullptr);
}